// round 4
// baseline (speedup 1.0000x reference)
#include <cuda_runtime.h>
#include <cstdint>
#include <cstddef>

#define D 128
#define NMAX 100032   // 100000 rounded up
#define EMAX 800000

// ---------------- scratch (device globals; no allocation allowed) ----------------
__device__ __align__(128) float g_degO[NMAX];            // -> inv sqrt deg_out
__device__ __align__(128) float g_degI[NMAX];            // -> inv sqrt deg_in
__device__ __align__(128) float g_agg[(size_t)NMAX * D]; // scatter accumulator
__device__ __align__(128) float g_h[(size_t)NMAX * D];   // layer-1 output
__device__ __align__(128) float g_Wt1[D * D];            // W1^T: Wt[k][j] = W[j][k]
__device__ __align__(128) float g_Wt2[D * D];
__device__ __align__(128) int   g_edges[2 * EMAX];       // normalized int32 edge list
__device__ int g_is64;                                   // 1 if input edges are int64

// ---------------- dtype probe: int64 vs int32 edge indices ----------------
__global__ void k_detect(const void* __restrict__ ei, int n) {
    const long long* e64 = (const long long*)ei;
    int ok = 1;
    for (int i = 0; i < 16; i++) {
        long long v = e64[i];
        if (v < 0 || v >= (long long)n) ok = 0;
    }
    g_is64 = ok;  // int32 read as int64 packs a 2nd random index into the
                  // high word -> out of range -> ok==0
}

__global__ void k_convert(const void* __restrict__ ei, int E) {
    int i = blockIdx.x * blockDim.x + threadIdx.x;
    if (i >= 2 * E) return;
    int v;
    if (g_is64) v = (int)((const long long*)ei)[i];
    else        v = ((const int*)ei)[i];
    g_edges[i] = v;
}

// ---------------- zeroing ----------------
__global__ void k_zero_all(int n) {
    size_t tid = (size_t)blockIdx.x * blockDim.x + threadIdx.x;
    size_t stride = (size_t)gridDim.x * blockDim.x;
    size_t total4 = (size_t)n * D / 4;
    float4 z = make_float4(0.f, 0.f, 0.f, 0.f);
    for (size_t p = tid; p < total4; p += stride)
        reinterpret_cast<float4*>(g_agg)[p] = z;
    for (size_t p = tid; p < (size_t)n; p += stride) {
        g_degO[p] = 0.f;
        g_degI[p] = 0.f;
    }
}

__global__ void k_zero_agg(int n) {
    size_t tid = (size_t)blockIdx.x * blockDim.x + threadIdx.x;
    size_t stride = (size_t)gridDim.x * blockDim.x;
    size_t total4 = (size_t)n * D / 4;
    float4 z = make_float4(0.f, 0.f, 0.f, 0.f);
    for (size_t p = tid; p < total4; p += stride)
        reinterpret_cast<float4*>(g_agg)[p] = z;
}

// ---------------- degree counting ----------------
__global__ void k_count_deg(int E) {
    int e = blockIdx.x * blockDim.x + threadIdx.x;
    if (e >= E) return;
    atomicAdd(&g_degO[g_edges[e]], 1.0f);       // integer-valued fp32: exact
    atomicAdd(&g_degI[g_edges[E + e]], 1.0f);
}

__global__ void k_finalize_deg(int n) {
    int i = blockIdx.x * blockDim.x + threadIdx.x;
    if (i >= n) return;
    g_degO[i] = rsqrtf(fmaxf(g_degO[i], 1.0f));
    g_degI[i] = rsqrtf(fmaxf(g_degI[i], 1.0f));
}

// ---------------- W transpose prep (tiny) ----------------
__global__ void k_transpose_w(const float* __restrict__ W1, const float* __restrict__ W2) {
    int i = blockIdx.x * blockDim.x + threadIdx.x;
    int which = i >= D * D;
    int idx = which ? i - D * D : i;
    int k = idx / D;
    int j = idx % D;
    const float* W = which ? W2 : W1;
    float* Wt = which ? g_Wt2 : g_Wt1;   // device-code symbol refs: valid
    Wt[k * D + j] = W[j * D + k];
}

// ---------------- scatter: agg[col] += src[row] * invdegO[row] ----------------
// one warp per edge, 32 lanes x float4 = 128 floats
template <bool FROM_H>
__global__ void k_scatter(const float* __restrict__ xin, int E) {
    int e = blockIdx.x * (blockDim.x >> 5) + (threadIdx.x >> 5);
    if (e >= E) return;
    int lane = threadIdx.x & 31;
    int row = g_edges[e];
    int col = g_edges[E + e];
    const float* src = FROM_H ? g_h : xin;
    float s = g_degO[row];
    float4 v = reinterpret_cast<const float4*>(src + (size_t)row * D)[lane];
    v.x *= s; v.y *= s; v.z *= s; v.w *= s;
    float* dst = g_agg + (size_t)col * D + lane * 4;
    asm volatile("red.global.add.v4.f32 [%0], {%1, %2, %3, %4};"
                 :: "l"(dst), "f"(v.x), "f"(v.y), "f"(v.z), "f"(v.w)
                 : "memory");
}

// ---------------- GEMM + fused epilogue ----------------
// out[i][j] = act( (sum_k agg[i][k]*W[j][k] + b[j]) * invdegI[i] [+ x[i][j]] )
// block tile 128x128, 256 threads as 16x16, 8x8 micro-tile per thread.
// Weight matrix selected INSIDE device code (g_Wt1/g_Wt2) — __device__ symbols
// must never be passed as host-side kernel args (ATS makes that silently read
// the zero-filled host shadow on GB300).
template <bool LAYER1>
__global__ __launch_bounds__(256, 2)
void k_gemm(const float* __restrict__ bias,
            const float* __restrict__ xres, float* __restrict__ outp, int n) {
    const int KC = 16;
    __shared__ float sW[KC][D];        // Wt chunk [kk][j]   8 KB
    __shared__ float sA[128][KC + 1];  // agg chunk [r][kk]  8.5 KB, padded

    const float* Wt = LAYER1 ? g_Wt1 : g_Wt2;

    const int tid = threadIdx.x;
    const int ty = tid >> 4;   // 0..15
    const int tx = tid & 15;   // 0..15
    const int rowBase = blockIdx.x * 128;

    float acc[8][8];
#pragma unroll
    for (int i = 0; i < 8; i++)
#pragma unroll
        for (int j = 0; j < 8; j++) acc[i][j] = 0.f;

    for (int k0 = 0; k0 < D; k0 += KC) {
        // sW: 16x128 floats = 512 float4, coalesced
#pragma unroll
        for (int it = 0; it < 2; it++) {
            int idx = tid + it * 256;          // 0..511
            int kk = idx >> 5;                 // 0..15
            int jj = idx & 31;                 // float4 col
            reinterpret_cast<float4*>(sW[kk])[jj] =
                reinterpret_cast<const float4*>(Wt + (size_t)(k0 + kk) * D)[jj];
        }
        // sA: 128 rows x 16 k
#pragma unroll
        for (int it = 0; it < 2; it++) {
            int idx = tid + it * 256;          // 0..511
            int r = idx >> 2;                  // 0..127
            int c = idx & 3;                   // float4 within 16 k
            int grow = rowBase + r;
            float4 v = make_float4(0.f, 0.f, 0.f, 0.f);
            if (grow < n)
                v = reinterpret_cast<const float4*>(g_agg + (size_t)grow * D + k0)[c];
            sA[r][c * 4 + 0] = v.x;
            sA[r][c * 4 + 1] = v.y;
            sA[r][c * 4 + 2] = v.z;
            sA[r][c * 4 + 3] = v.w;
        }
        __syncthreads();

#pragma unroll
        for (int kk = 0; kk < KC; kk++) {
            float a[8];
#pragma unroll
            for (int i = 0; i < 8; i++) a[i] = sA[ty * 8 + i][kk];
            float4 w0 = reinterpret_cast<float4*>(sW[kk])[tx * 2];
            float4 w1 = reinterpret_cast<float4*>(sW[kk])[tx * 2 + 1];
#pragma unroll
            for (int i = 0; i < 8; i++) {
                acc[i][0] += a[i] * w0.x;
                acc[i][1] += a[i] * w0.y;
                acc[i][2] += a[i] * w0.z;
                acc[i][3] += a[i] * w0.w;
                acc[i][4] += a[i] * w1.x;
                acc[i][5] += a[i] * w1.y;
                acc[i][6] += a[i] * w1.z;
                acc[i][7] += a[i] * w1.w;
            }
        }
        __syncthreads();
    }

    float4 b0 = reinterpret_cast<const float4*>(bias)[tx * 2];
    float4 b1 = reinterpret_cast<const float4*>(bias)[tx * 2 + 1];
    float* out = LAYER1 ? g_h : outp;

#pragma unroll
    for (int i = 0; i < 8; i++) {
        int grow = rowBase + ty * 8 + i;
        if (grow >= n) continue;
        float inv = g_degI[grow];
        float4 o0, o1;
        o0.x = (acc[i][0] + b0.x) * inv;
        o0.y = (acc[i][1] + b0.y) * inv;
        o0.z = (acc[i][2] + b0.z) * inv;
        o0.w = (acc[i][3] + b0.w) * inv;
        o1.x = (acc[i][4] + b1.x) * inv;
        o1.y = (acc[i][5] + b1.y) * inv;
        o1.z = (acc[i][6] + b1.z) * inv;
        o1.w = (acc[i][7] + b1.w) * inv;
        if (LAYER1) {
            float4 x0 = reinterpret_cast<const float4*>(xres + (size_t)grow * D)[tx * 2];
            float4 x1 = reinterpret_cast<const float4*>(xres + (size_t)grow * D)[tx * 2 + 1];
            o0.x = fmaxf(o0.x + x0.x, 0.f);
            o0.y = fmaxf(o0.y + x0.y, 0.f);
            o0.z = fmaxf(o0.z + x0.z, 0.f);
            o0.w = fmaxf(o0.w + x0.w, 0.f);
            o1.x = fmaxf(o1.x + x1.x, 0.f);
            o1.y = fmaxf(o1.y + x1.y, 0.f);
            o1.z = fmaxf(o1.z + x1.z, 0.f);
            o1.w = fmaxf(o1.w + x1.w, 0.f);
        }
        reinterpret_cast<float4*>(out + (size_t)grow * D)[tx * 2] = o0;
        reinterpret_cast<float4*>(out + (size_t)grow * D)[tx * 2 + 1] = o1;
    }
}

// ---------------- launch ----------------
extern "C" void kernel_launch(void* const* d_in, const int* in_sizes, int n_in,
                              void* d_out, int out_size) {
    const float* x  = (const float*)d_in[0];
    const void*  ei = d_in[1];
    const float* b1 = (const float*)d_in[3];
    const float* W1 = (const float*)d_in[2];
    const float* W2 = (const float*)d_in[4];
    const float* b2 = (const float*)d_in[5];
    float* out      = (float*)d_out;

    const int n = in_sizes[0] / D;   // 100000
    const int E = in_sizes[1] / 2;   // 800000

    const int ZB = 2048;
    const int CB = (E + 255) / 256;
    const int FB = (n + 255) / 256;
    const int SB = (E + 7) / 8;                  // scatter: 8 warps/block
    const int GB = (n + 127) / 128;              // gemm: 128-row tiles

    // prep
    k_detect<<<1, 1>>>(ei, n);
    k_convert<<<(2 * E + 255) / 256, 256>>>(ei, E);
    k_zero_all<<<ZB, 256>>>(n);
    k_transpose_w<<<(2 * D * D + 255) / 256, 256>>>(W1, W2);
    k_count_deg<<<CB, 256>>>(E);
    k_finalize_deg<<<FB, 256>>>(n);

    // layer 1: scatter(x * invO) -> agg; h = relu((agg@W1^T + b1)*invI + x)
    k_scatter<false><<<SB, 256>>>(x, E);
    k_gemm<true><<<GB, 256>>>(b1, x, nullptr, n);

    // layer 2: scatter(h * invO) -> agg; out = (agg@W2^T + b2)*invI
    k_zero_agg<<<ZB, 256>>>(n);
    k_scatter<true><<<SB, 256>>>(nullptr, E);
    k_gemm<false><<<GB, 256>>>(b2, nullptr, out, n);
}

// round 5
// speedup vs baseline: 1.2402x; 1.2402x over previous
#include <cuda_runtime.h>
#include <cstdint>
#include <cstddef>

#define D 128
#define NMAX 100032   // 100000 rounded up
#define EMAX 800000
#define NB_SCAN ((NMAX + 255) / 256)   // 391 blocks

// ---------------- scratch (device globals; no allocation allowed) ----------------
__device__ __align__(128) float g_degO[NMAX];            // inv sqrt deg_out
__device__ __align__(128) float g_degI[NMAX];            // inv sqrt deg_in
__device__ __align__(128) int   g_cntO[NMAX];
__device__ __align__(128) int   g_cntI[NMAX];
__device__ __align__(128) int   g_scan[NMAX];            // inclusive in-block scan of cntI
__device__ __align__(128) int   g_bsum[512];             // per-block sums
__device__ __align__(128) int   g_off[NMAX + 1];         // CSR offsets (by dest)
__device__ __align__(128) int   g_cur[NMAX];             // bucket cursors
__device__ __align__(128) int   g_csrc[EMAX];            // CSR source-node list
__device__ __align__(128) float g_agg[(size_t)NMAX * D]; // aggregated messages
__device__ __align__(128) float g_h[(size_t)NMAX * D];   // layer-1 output
__device__ __align__(128) float g_Wt1[D * D];            // W1^T
__device__ __align__(128) float g_Wt2[D * D];
__device__ __align__(128) int   g_edges[2 * EMAX];       // normalized int32 edges
__device__ int g_is64;

// ---------------- dtype probe: int64 vs int32 edge indices ----------------
__global__ void k_detect(const void* __restrict__ ei, int n) {
    const long long* e64 = (const long long*)ei;
    int ok = 1;
    for (int i = 0; i < 16; i++) {
        long long v = e64[i];
        if (v < 0 || v >= (long long)n) ok = 0;
    }
    g_is64 = ok;
}

__global__ void k_convert(const void* __restrict__ ei, int E) {
    int i = blockIdx.x * blockDim.x + threadIdx.x;
    if (i >= 2 * E) return;
    int v;
    if (g_is64) v = (int)((const long long*)ei)[i];
    else        v = ((const int*)ei)[i];
    g_edges[i] = v;
}

// ---------------- degree counting ----------------
__global__ void k_zero_cnt(int n) {
    int i = blockIdx.x * blockDim.x + threadIdx.x;
    if (i < n) { g_cntO[i] = 0; g_cntI[i] = 0; }
}

__global__ void k_count_deg(int E) {
    int e = blockIdx.x * blockDim.x + threadIdx.x;
    if (e >= E) return;
    atomicAdd(&g_cntO[g_edges[e]], 1);
    atomicAdd(&g_cntI[g_edges[E + e]], 1);
}

__global__ void k_finalize_deg(int n) {
    int i = blockIdx.x * blockDim.x + threadIdx.x;
    if (i >= n) return;
    g_degO[i] = rsqrtf((float)max(g_cntO[i], 1));
    g_degI[i] = rsqrtf((float)max(g_cntI[i], 1));
}

// ---------------- CSR offsets: 3-step scan over cntI ----------------
__global__ void k_scan1(int n) {   // per-block inclusive scan, 256/block
    __shared__ int s[256];
    int i = blockIdx.x * 256 + threadIdx.x;
    int v = (i < n) ? g_cntI[i] : 0;
    s[threadIdx.x] = v;
    __syncthreads();
#pragma unroll
    for (int off = 1; off < 256; off <<= 1) {
        int t = (threadIdx.x >= off) ? s[threadIdx.x - off] : 0;
        __syncthreads();
        s[threadIdx.x] += t;
        __syncthreads();
    }
    if (i < n) g_scan[i] = s[threadIdx.x];
    if (threadIdx.x == 255) g_bsum[blockIdx.x] = s[255];
}

__global__ void k_scan2(int nb) {  // one block: exclusive scan of block sums
    __shared__ int s[512];
    int t = threadIdx.x;
    s[t] = (t < nb) ? g_bsum[t] : 0;
    __syncthreads();
#pragma unroll
    for (int off = 1; off < 512; off <<= 1) {
        int v = (t >= off) ? s[t - off] : 0;
        __syncthreads();
        s[t] += v;
        __syncthreads();
    }
    if (t < nb) g_bsum[t] = s[t] - ((t < nb) ? 0 : 0) - ( (t < 512) ? ((t==0)?s[0]:s[t]-s[t-1]) : 0 ) + ((t == 0) ? 0 : s[t - 1]) - ((t==0)?0:s[t-1]);
    // simplify: exclusive = inclusive - own value; own value = s[t]-s[t-1] (t>0) or s[0]
    // rewrite cleanly below
    __syncthreads();
    if (t < nb) g_bsum[t] = (t == 0) ? 0 : s[t - 1];
}

__global__ void k_scan3(int n, int E) {  // offsets + cursors
    int i = blockIdx.x * 256 + threadIdx.x;
    if (i < n) {
        int off = g_bsum[blockIdx.x] + g_scan[i] - g_cntI[i];  // exclusive
        g_off[i] = off;
        g_cur[i] = off;
    }
    if (i == 0) g_off[n] = E;
}

// ---------------- bucket edges into CSR ----------------
__global__ void k_bucket(int E) {
    int e = blockIdx.x * blockDim.x + threadIdx.x;
    if (e >= E) return;
    int col = g_edges[E + e];
    int pos = atomicAdd(&g_cur[col], 1);
    g_csrc[pos] = g_edges[e];
}

// ---------------- W transpose prep ----------------
__global__ void k_transpose_w(const float* __restrict__ W1, const float* __restrict__ W2) {
    int i = blockIdx.x * blockDim.x + threadIdx.x;
    int which = i >= D * D;
    int idx = which ? i - D * D : i;
    int k = idx / D;
    int j = idx % D;
    const float* W = which ? W2 : W1;
    float* Wt = which ? g_Wt2 : g_Wt1;
    Wt[k * D + j] = W[j * D + k];
}

// ---------------- gather: agg[v] = sum_{(u->v)} src[u] * invdegO[u] ----------------
// one warp per destination node, 4 floats (1 float4) per lane, 2-edge unroll
template <bool FROM_H>
__global__ void k_gather(const float* __restrict__ xin, int n) {
    int v = blockIdx.x * (blockDim.x >> 5) + (threadIdx.x >> 5);
    if (v >= n) return;
    int lane = threadIdx.x & 31;
    const float* src = FROM_H ? g_h : xin;

    int p   = g_off[v];
    int end = g_off[v + 1];

    float4 acc0 = make_float4(0.f, 0.f, 0.f, 0.f);
    float4 acc1 = make_float4(0.f, 0.f, 0.f, 0.f);

    for (; p + 1 < end; p += 2) {
        int u0 = g_csrc[p];
        int u1 = g_csrc[p + 1];
        float s0 = g_degO[u0];
        float s1 = g_degO[u1];
        float4 a = reinterpret_cast<const float4*>(src + (size_t)u0 * D)[lane];
        float4 b = reinterpret_cast<const float4*>(src + (size_t)u1 * D)[lane];
        acc0.x += a.x * s0; acc0.y += a.y * s0; acc0.z += a.z * s0; acc0.w += a.w * s0;
        acc1.x += b.x * s1; acc1.y += b.y * s1; acc1.z += b.z * s1; acc1.w += b.w * s1;
    }
    if (p < end) {
        int u0 = g_csrc[p];
        float s0 = g_degO[u0];
        float4 a = reinterpret_cast<const float4*>(src + (size_t)u0 * D)[lane];
        acc0.x += a.x * s0; acc0.y += a.y * s0; acc0.z += a.z * s0; acc0.w += a.w * s0;
    }
    acc0.x += acc1.x; acc0.y += acc1.y; acc0.z += acc1.z; acc0.w += acc1.w;
    reinterpret_cast<float4*>(g_agg + (size_t)v * D)[lane] = acc0;
}

// ---------------- GEMM + fused epilogue ----------------
// out[i][j] = act( (sum_k agg[i][k]*W[j][k] + b[j]) * invdegI[i] [+ x[i][j]] )
// block tile 128x128, 256 threads as 16x16, 8x8 micro-tile per thread.
template <bool LAYER1>
__global__ __launch_bounds__(256, 2)
void k_gemm(const float* __restrict__ bias,
            const float* __restrict__ xres, float* __restrict__ outp, int n) {
    const int KC = 16;
    __shared__ float sW[KC][D];
    __shared__ float sA[128][KC + 1];

    const float* Wt = LAYER1 ? g_Wt1 : g_Wt2;   // device-side symbol selection

    const int tid = threadIdx.x;
    const int ty = tid >> 4;
    const int tx = tid & 15;
    const int rowBase = blockIdx.x * 128;

    float acc[8][8];
#pragma unroll
    for (int i = 0; i < 8; i++)
#pragma unroll
        for (int j = 0; j < 8; j++) acc[i][j] = 0.f;

    for (int k0 = 0; k0 < D; k0 += KC) {
#pragma unroll
        for (int it = 0; it < 2; it++) {
            int idx = tid + it * 256;
            int kk = idx >> 5;
            int jj = idx & 31;
            reinterpret_cast<float4*>(sW[kk])[jj] =
                reinterpret_cast<const float4*>(Wt + (size_t)(k0 + kk) * D)[jj];
        }
#pragma unroll
        for (int it = 0; it < 2; it++) {
            int idx = tid + it * 256;
            int r = idx >> 2;
            int c = idx & 3;
            int grow = rowBase + r;
            float4 v = make_float4(0.f, 0.f, 0.f, 0.f);
            if (grow < n)
                v = reinterpret_cast<const float4*>(g_agg + (size_t)grow * D + k0)[c];
            sA[r][c * 4 + 0] = v.x;
            sA[r][c * 4 + 1] = v.y;
            sA[r][c * 4 + 2] = v.z;
            sA[r][c * 4 + 3] = v.w;
        }
        __syncthreads();

#pragma unroll
        for (int kk = 0; kk < KC; kk++) {
            float a[8];
#pragma unroll
            for (int i = 0; i < 8; i++) a[i] = sA[ty * 8 + i][kk];
            float4 w0 = reinterpret_cast<float4*>(sW[kk])[tx * 2];
            float4 w1 = reinterpret_cast<float4*>(sW[kk])[tx * 2 + 1];
#pragma unroll
            for (int i = 0; i < 8; i++) {
                acc[i][0] += a[i] * w0.x;
                acc[i][1] += a[i] * w0.y;
                acc[i][2] += a[i] * w0.z;
                acc[i][3] += a[i] * w0.w;
                acc[i][4] += a[i] * w1.x;
                acc[i][5] += a[i] * w1.y;
                acc[i][6] += a[i] * w1.z;
                acc[i][7] += a[i] * w1.w;
            }
        }
        __syncthreads();
    }

    float4 b0 = reinterpret_cast<const float4*>(bias)[tx * 2];
    float4 b1 = reinterpret_cast<const float4*>(bias)[tx * 2 + 1];
    float* out = LAYER1 ? g_h : outp;

#pragma unroll
    for (int i = 0; i < 8; i++) {
        int grow = rowBase + ty * 8 + i;
        if (grow >= n) continue;
        float inv = g_degI[grow];
        float4 o0, o1;
        o0.x = (acc[i][0] + b0.x) * inv;
        o0.y = (acc[i][1] + b0.y) * inv;
        o0.z = (acc[i][2] + b0.z) * inv;
        o0.w = (acc[i][3] + b0.w) * inv;
        o1.x = (acc[i][4] + b1.x) * inv;
        o1.y = (acc[i][5] + b1.y) * inv;
        o1.z = (acc[i][6] + b1.z) * inv;
        o1.w = (acc[i][7] + b1.w) * inv;
        if (LAYER1) {
            float4 x0 = reinterpret_cast<const float4*>(xres + (size_t)grow * D)[tx * 2];
            float4 x1 = reinterpret_cast<const float4*>(xres + (size_t)grow * D)[tx * 2 + 1];
            o0.x = fmaxf(o0.x + x0.x, 0.f);
            o0.y = fmaxf(o0.y + x0.y, 0.f);
            o0.z = fmaxf(o0.z + x0.z, 0.f);
            o0.w = fmaxf(o0.w + x0.w, 0.f);
            o1.x = fmaxf(o1.x + x1.x, 0.f);
            o1.y = fmaxf(o1.y + x1.y, 0.f);
            o1.z = fmaxf(o1.z + x1.z, 0.f);
            o1.w = fmaxf(o1.w + x1.w, 0.f);
        }
        reinterpret_cast<float4*>(out + (size_t)grow * D)[tx * 2] = o0;
        reinterpret_cast<float4*>(out + (size_t)grow * D)[tx * 2 + 1] = o1;
    }
}

// ---------------- launch ----------------
extern "C" void kernel_launch(void* const* d_in, const int* in_sizes, int n_in,
                              void* d_out, int out_size) {
    const float* x  = (const float*)d_in[0];
    const void*  ei = d_in[1];
    const float* W1 = (const float*)d_in[2];
    const float* b1 = (const float*)d_in[3];
    const float* W2 = (const float*)d_in[4];
    const float* b2 = (const float*)d_in[5];
    float* out      = (float*)d_out;

    const int n = in_sizes[0] / D;   // 100000
    const int E = in_sizes[1] / 2;   // 800000

    const int CB = (E + 255) / 256;
    const int FB = (n + 255) / 256;
    const int NB = (n + 255) / 256;              // scan blocks (<=512)
    const int GAB = (n + 7) / 8;                 // gather: 8 warps/block
    const int GB = (n + 127) / 128;              // gemm: 128-row tiles

    // prep: edges, weights, degrees, CSR
    k_detect<<<1, 1>>>(ei, n);
    k_convert<<<(2 * E + 255) / 256, 256>>>(ei, E);
    k_zero_cnt<<<FB, 256>>>(n);
    k_transpose_w<<<(2 * D * D + 255) / 256, 256>>>(W1, W2);
    k_count_deg<<<CB, 256>>>(E);
    k_finalize_deg<<<FB, 256>>>(n);
    k_scan1<<<NB, 256>>>(n);
    k_scan2<<<1, 512>>>(NB);
    k_scan3<<<NB, 256>>>(n, E);
    k_bucket<<<CB, 256>>>(E);

    // layer 1: gather(x * invO) -> agg; h = relu((agg@W1^T + b1)*invI + x)
    k_gather<false><<<GAB, 256>>>(x, n);
    k_gemm<true><<<GB, 256>>>(b1, x, nullptr, n);

    // layer 2: gather(h * invO) -> agg; out = (agg@W2^T + b2)*invI
    k_gather<true><<<GAB, 256>>>(nullptr, n);
    k_gemm<false><<<GB, 256>>>(b2, nullptr, out, n);
}